// round 2
// baseline (speedup 1.0000x reference)
#include <cuda_runtime.h>

#define BB   2048
#define HIST 50
#define DIM  64
#define SS   32

__device__ float g_user[BB*DIM];
__device__ float g_scores[BB];
__device__ float g_maxn;

// ---------------------------------------------------------------------------
// K1: max(n_idxs)
// ---------------------------------------------------------------------------
__global__ void k_maxn(const int* __restrict__ n_idxs) {
    __shared__ int sm[256];
    int m = 0;
    for (int i = threadIdx.x; i < BB; i += 256) m = max(m, __ldg(n_idxs + i));
    sm[threadIdx.x] = m;
    __syncthreads();
    for (int s = 128; s > 0; s >>= 1) {
        if (threadIdx.x < s) sm[threadIdx.x] = max(sm[threadIdx.x], sm[threadIdx.x + s]);
        __syncthreads();
    }
    if (threadIdx.x == 0) g_maxn = (float)sm[0];
}

// ---------------------------------------------------------------------------
// K2: user embedding. grid=B, block=128. i=float4 lane (16), h=history slice (8)
// ---------------------------------------------------------------------------
__global__ void __launch_bounds__(128) k_user(const int* __restrict__ user_inputs,
                                              const int* __restrict__ n_idxs,
                                              const float* __restrict__ emb) {
    __shared__ float4 red[8][16];
    int b = blockIdx.x, t = threadIdx.x;
    int i = t & 15, h = t >> 4;
    int n = __ldg(n_idxs + b);
    const float4* emb4 = (const float4*)emb;
    const int* row = user_inputs + b * HIST;
    float4 acc = make_float4(0.f, 0.f, 0.f, 0.f);
    for (int p = h; p < n; p += 8) {
        int idx = __ldg(row + p);
        float4 v = __ldg(emb4 + (size_t)idx * 16 + i);
        acc.x += v.x; acc.y += v.y; acc.z += v.z; acc.w += v.w;
    }
    red[h][i] = acc;
    __syncthreads();
    if (h == 0) {
        float4 s = red[0][i];
        #pragma unroll
        for (int q = 1; q < 8; q++) {
            float4 v = red[q][i];
            s.x += v.x; s.y += v.y; s.z += v.z; s.w += v.w;
        }
        float inv = 1.f / g_maxn;
        s.x *= inv; s.y *= inv; s.z *= inv; s.w *= inv;
        ((float4*)g_user)[(size_t)b * 16 + i] = s;
    }
}

// ---------------------------------------------------------------------------
// K3 (fused): one block per batch item. 512 threads.
//   Phase 1: level-0 softmax (warp 0) + 32 level-1 softmaxes (2 per warp)
//   Phase 2: gathers -> s_x (self||agg per node)
//   Phase 3: big MLP (32 nodes x 64 outs) -> s_h1
//   Phase 4: level-0 aggregations (agg1 over selfs, agg2 over h1)
//   Phase 5-7: pool1 MLP, pool2 MLP, fc1/fc2 -> g_scores[b]
// ---------------------------------------------------------------------------
__global__ void __launch_bounds__(512) k_main(
    const int*   __restrict__ item_inputs,
    const int*   __restrict__ adj_item,
    const float* __restrict__ adj_adam,
    const float* __restrict__ emb,
    const float* __restrict__ pool_w,   // [128][64]
    const float* __restrict__ pool_b,   // [64]
    const float* __restrict__ fc1_w,    // [128][32]
    const float* __restrict__ fc1_b,    // [32]
    const float* __restrict__ fc2_w,    // [32]
    const float* __restrict__ fc2_b)    // [1]
{
    __shared__ float  s_w1[SS][SS];     // 4 KB  level-1 softmax weights
    __shared__ int    s_nbr[SS][SS];    // 4 KB  level-2 neighbor ids
    __shared__ int    s_e[SS];          // level-1 node ids
    __shared__ float  s_w0[SS];         // level-0 softmax weights
    __shared__ float4 s_x4[SS][32];     // 16 KB [g][0..15]=self, [16..31]=agg
    __shared__ float4 s_h14[SS][16];    // 8 KB  pooled level-1 vectors
    __shared__ float  s_p1x[2*DIM];     // pool1 input
    __shared__ float  s_p2x[2*DIM];     // pool2 input
    __shared__ float  s_fcx[2*DIM];     // fc input

    int b = blockIdx.x, t = threadIdx.x;
    int warp = t >> 5, lane = t & 31;
    int item = __ldg(item_inputs + b);

    // ---- Phase 1: softmaxes ----
    #pragma unroll
    for (int q = 0; q < 2; q++) {
        int g = warp * 2 + q;
        int e = __ldg(adj_item + (size_t)item * SS + g);   // uniform per warp
        float a  = __ldg(adj_adam + (size_t)e * SS + lane);
        int  nbr = __ldg(adj_item + (size_t)e * SS + lane);
        float m = a;
        #pragma unroll
        for (int o = 16; o > 0; o >>= 1) m = fmaxf(m, __shfl_xor_sync(0xffffffffu, m, o));
        float ex = expf(a - m);
        float ssum = ex;
        #pragma unroll
        for (int o = 16; o > 0; o >>= 1) ssum += __shfl_xor_sync(0xffffffffu, ssum, o);
        s_w1[g][lane]  = ex / ssum;
        s_nbr[g][lane] = nbr;
        if (lane == 0) s_e[g] = e;
    }
    if (warp == 0) {
        float a = __ldg(adj_adam + (size_t)item * SS + lane);
        float m = a;
        #pragma unroll
        for (int o = 16; o > 0; o >>= 1) m = fmaxf(m, __shfl_xor_sync(0xffffffffu, m, o));
        float ex = expf(a - m);
        float ssum = ex;
        #pragma unroll
        for (int o = 16; o > 0; o >>= 1) ssum += __shfl_xor_sync(0xffffffffu, ssum, o);
        s_w0[lane] = ex / ssum;
    }
    __syncthreads();

    // ---- Phase 2: gathers ----
    int g = t >> 4, i = t & 15;
    const float4* emb4 = (const float4*)emb;
    float4 self4 = __ldg(emb4 + (size_t)s_e[g] * 16 + i);
    float4 agg = make_float4(0.f, 0.f, 0.f, 0.f);
    #pragma unroll 8
    for (int j = 0; j < SS; j++) {
        float  wj = s_w1[g][j];
        float4 v  = __ldg(emb4 + (size_t)s_nbr[g][j] * 16 + i);
        agg.x += wj * v.x; agg.y += wj * v.y; agg.z += wj * v.z; agg.w += wj * v.w;
    }
    s_x4[g][i]      = self4;
    s_x4[g][16 + i] = agg;
    __syncthreads();

    // ---- Phase 3: big MLP, out[4i..4i+3] for node g ----
    const float4* pw4 = (const float4*)pool_w;
    float4 acc = __ldg(((const float4*)pool_b) + i);
    #pragma unroll 8
    for (int k4 = 0; k4 < 32; k4++) {
        float4 xv = s_x4[g][k4];
        float4 wA = __ldg(pw4 + (size_t)(k4 * 4 + 0) * 16 + i);
        acc.x += xv.x * wA.x; acc.y += xv.x * wA.y; acc.z += xv.x * wA.z; acc.w += xv.x * wA.w;
        float4 wB = __ldg(pw4 + (size_t)(k4 * 4 + 1) * 16 + i);
        acc.x += xv.y * wB.x; acc.y += xv.y * wB.y; acc.z += xv.y * wB.z; acc.w += xv.y * wB.w;
        float4 wC = __ldg(pw4 + (size_t)(k4 * 4 + 2) * 16 + i);
        acc.x += xv.z * wC.x; acc.y += xv.z * wC.y; acc.z += xv.z * wC.z; acc.w += xv.z * wC.w;
        float4 wD = __ldg(pw4 + (size_t)(k4 * 4 + 3) * 16 + i);
        acc.x += xv.w * wD.x; acc.y += xv.w * wD.y; acc.z += xv.w * wD.z; acc.w += xv.w * wD.w;
    }
    s_h14[g][i] = make_float4(fmaxf(acc.x, 0.f), fmaxf(acc.y, 0.f),
                              fmaxf(acc.z, 0.f), fmaxf(acc.w, 0.f));
    __syncthreads();

    // ---- Phase 4: level-0 aggregations + load emb[item] ----
    if (t < 128) {
        int d = t & 63, which = t >> 6;
        float sum = 0.f;
        if (which == 0) {
            const float* sx = (const float*)s_x4;   // row stride 128 floats; self = [0..63]
            #pragma unroll 8
            for (int g2 = 0; g2 < SS; g2++) sum += s_w0[g2] * sx[g2 * 128 + d];
            s_p1x[DIM + d] = sum;
        } else {
            const float* sh = (const float*)s_h14;  // row stride 64 floats
            #pragma unroll 8
            for (int g2 = 0; g2 < SS; g2++) sum += s_w0[g2] * sh[g2 * 64 + d];
            s_p2x[DIM + d] = sum;
        }
    } else if (t >= 128 && t < 192) {
        int d = t - 128;
        s_p1x[d] = __ldg(emb + (size_t)item * DIM + d);
        s_fcx[d] = g_user[b * DIM + d];
    }
    __syncthreads();

    // ---- Phase 5: pool1 MLP -> h0 ----
    if (t < 64) {
        float h0 = __ldg(pool_b + t);
        const float4* x4 = (const float4*)s_p1x;
        #pragma unroll 8
        for (int k4 = 0; k4 < 32; k4++) {
            float4 xv = x4[k4];
            h0 += xv.x * __ldg(pool_w + (k4 * 4 + 0) * DIM + t);
            h0 += xv.y * __ldg(pool_w + (k4 * 4 + 1) * DIM + t);
            h0 += xv.z * __ldg(pool_w + (k4 * 4 + 2) * DIM + t);
            h0 += xv.w * __ldg(pool_w + (k4 * 4 + 3) * DIM + t);
        }
        s_p2x[t] = fmaxf(h0, 0.f);
    }
    __syncthreads();

    // ---- Phase 6: pool2 MLP -> item_emb ----
    if (t < 64) {
        float v = __ldg(pool_b + t);
        const float4* x4 = (const float4*)s_p2x;
        #pragma unroll 8
        for (int k4 = 0; k4 < 32; k4++) {
            float4 xv = x4[k4];
            v += xv.x * __ldg(pool_w + (k4 * 4 + 0) * DIM + t);
            v += xv.y * __ldg(pool_w + (k4 * 4 + 1) * DIM + t);
            v += xv.z * __ldg(pool_w + (k4 * 4 + 2) * DIM + t);
            v += xv.w * __ldg(pool_w + (k4 * 4 + 3) * DIM + t);
        }
        s_fcx[DIM + t] = fmaxf(v, 0.f);
    }
    __syncthreads();

    // ---- Phase 7: fc1 -> relu -> fc2 -> score ----
    if (t < 32) {
        float y = __ldg(fc1_b + t);
        const float4* x4 = (const float4*)s_fcx;
        #pragma unroll 8
        for (int k4 = 0; k4 < 32; k4++) {
            float4 xv = x4[k4];
            y += xv.x * __ldg(fc1_w + (k4 * 4 + 0) * 32 + t);
            y += xv.y * __ldg(fc1_w + (k4 * 4 + 1) * 32 + t);
            y += xv.z * __ldg(fc1_w + (k4 * 4 + 2) * 32 + t);
            y += xv.w * __ldg(fc1_w + (k4 * 4 + 3) * 32 + t);
        }
        y = fmaxf(y, 0.f);
        float p = y * __ldg(fc2_w + t);
        #pragma unroll
        for (int o = 16; o > 0; o >>= 1) p += __shfl_xor_sync(0xffffffffu, p, o);
        if (t == 0) g_scores[b] = p + __ldg(fc2_b);
    }
}

// ---------------------------------------------------------------------------
// K4: batch softmax -> d_out
// ---------------------------------------------------------------------------
__global__ void k_softmax(float* __restrict__ out) {
    __shared__ float red[1024];
    int t = threadIdx.x;
    float a0 = g_scores[t];
    float a1 = g_scores[t + 1024];

    red[t] = fmaxf(a0, a1);
    __syncthreads();
    for (int s = 512; s > 0; s >>= 1) {
        if (t < s) red[t] = fmaxf(red[t], red[t + s]);
        __syncthreads();
    }
    float gm = red[0];
    __syncthreads();

    float e0 = expf(a0 - gm), e1 = expf(a1 - gm);
    red[t] = e0 + e1;
    __syncthreads();
    for (int s = 512; s > 0; s >>= 1) {
        if (t < s) red[t] += red[t + s];
        __syncthreads();
    }
    float inv = 1.f / red[0];
    out[t]        = e0 * inv;
    out[t + 1024] = e1 * inv;
}

// ---------------------------------------------------------------------------
extern "C" void kernel_launch(void* const* d_in, const int* in_sizes, int n_in,
                              void* d_out, int out_size) {
    const int*   user_inputs = (const int*)  d_in[0];
    const int*   item_inputs = (const int*)  d_in[1];
    const int*   n_idxs      = (const int*)  d_in[2];
    const float* emb         = (const float*)d_in[3];
    const int*   adj_item    = (const int*)  d_in[4];
    const float* adj_adam    = (const float*)d_in[5];
    const float* pool_w      = (const float*)d_in[6];
    const float* pool_b      = (const float*)d_in[7];
    const float* fc1_w       = (const float*)d_in[8];
    const float* fc1_b       = (const float*)d_in[9];
    const float* fc2_w       = (const float*)d_in[10];
    const float* fc2_b       = (const float*)d_in[11];
    float* out = (float*)d_out;

    k_maxn<<<1, 256>>>(n_idxs);
    k_user<<<BB, 128>>>(user_inputs, n_idxs, emb);
    k_main<<<BB, 512>>>(item_inputs, adj_item, adj_adam, emb,
                        pool_w, pool_b, fc1_w, fc1_b, fc2_w, fc2_b);
    k_softmax<<<1, 1024>>>(out);
}

// round 4
// speedup vs baseline: 1.3620x; 1.3620x over previous
#include <cuda_runtime.h>

#define BB   2048
#define HIST 50
#define DIM  64
#define SS   32

__device__ float g_user[BB*DIM];
__device__ float g_h1[(size_t)BB*SS*DIM];   // 16 MB level-1 pooled vectors
__device__ float g_scores[BB];
__device__ float g_maxn;

// ---------------------------------------------------------------------------
// K1: max(n_idxs)
// ---------------------------------------------------------------------------
__global__ void k_maxn(const int* __restrict__ n_idxs) {
    __shared__ int sm[256];
    int m = 0;
    for (int i = threadIdx.x; i < BB; i += 256) m = max(m, __ldg(n_idxs + i));
    sm[threadIdx.x] = m;
    __syncthreads();
    for (int s = 128; s > 0; s >>= 1) {
        if (threadIdx.x < s) sm[threadIdx.x] = max(sm[threadIdx.x], sm[threadIdx.x + s]);
        __syncthreads();
    }
    if (threadIdx.x == 0) g_maxn = (float)sm[0];
}

// ---------------------------------------------------------------------------
// K2: user embedding. grid=B, block=128. i=float4 lane (16), h=history slice (8)
// ---------------------------------------------------------------------------
__global__ void __launch_bounds__(128) k_user(const int* __restrict__ user_inputs,
                                              const int* __restrict__ n_idxs,
                                              const float* __restrict__ emb) {
    __shared__ float4 red[8][16];
    int b = blockIdx.x, t = threadIdx.x;
    int i = t & 15, h = t >> 4;
    int n = __ldg(n_idxs + b);
    const float4* emb4 = (const float4*)emb;
    const int* row = user_inputs + b * HIST;
    float4 acc = make_float4(0.f, 0.f, 0.f, 0.f);
    for (int p = h; p < n; p += 8) {
        int idx = __ldg(row + p);
        float4 v = __ldg(emb4 + (size_t)idx * 16 + i);
        acc.x += v.x; acc.y += v.y; acc.z += v.z; acc.w += v.w;
    }
    red[h][i] = acc;
    __syncthreads();
    if (h == 0) {
        float4 s = red[0][i];
        #pragma unroll
        for (int q = 1; q < 8; q++) {
            float4 v = red[q][i];
            s.x += v.x; s.y += v.y; s.z += v.z; s.w += v.w;
        }
        float inv = 1.f / g_maxn;
        s.x *= inv; s.y *= inv; s.z *= inv; s.w *= inv;
        ((float4*)g_user)[(size_t)b * 16 + i] = s;
    }
}

// ---------------------------------------------------------------------------
// K3: level-1 pooling, 8 nodes per 128-thread block. grid = 65536/8 = 8192.
// MLP: thread (i = output quad, half = k-slice of 8) applies each weight load
// to ALL 8 nodes -> 8x less L1 weight traffic. Partial-sum reduce via smem.
// ---------------------------------------------------------------------------
__global__ void __launch_bounds__(128) k_h1(
    const int*   __restrict__ item_inputs,
    const int*   __restrict__ adj_item,
    const float* __restrict__ adj_adam,
    const float* __restrict__ emb,
    const float* __restrict__ pool_w,   // [128][64]
    const float* __restrict__ pool_b)   // [64]
{
    __shared__ float  s_w1[8][SS];
    __shared__ int    s_nbr[8][SS];
    __shared__ int    s_e[8];
    __shared__ float4 buf[1024];        // 16 KB: x-tiles then MLP partials

    int t = threadIdx.x, warp = t >> 5, lane = t & 31;
    int node0 = blockIdx.x * 8;
    int b = node0 >> 5;
    int nn0 = node0 & 31;
    int item = __ldg(item_inputs + b);

    // Phase 1: 8 level-1 softmaxes (2 per warp)
    #pragma unroll
    for (int q = 0; q < 2; q++) {
        int ni = warp * 2 + q;
        int e  = __ldg(adj_item + (size_t)item * SS + nn0 + ni);
        float a  = __ldg(adj_adam + (size_t)e * SS + lane);
        int  nbr = __ldg(adj_item + (size_t)e * SS + lane);
        float m = a;
        #pragma unroll
        for (int o = 16; o > 0; o >>= 1) m = fmaxf(m, __shfl_xor_sync(0xffffffffu, m, o));
        float ex = expf(a - m);
        float ssum = ex;
        #pragma unroll
        for (int o = 16; o > 0; o >>= 1) ssum += __shfl_xor_sync(0xffffffffu, ssum, o);
        s_w1[ni][lane]  = ex / ssum;
        s_nbr[ni][lane] = nbr;
        if (lane == 0) s_e[ni] = e;
    }
    __syncthreads();

    // Phase 2: gathers. thread: ni = t/16 (node), i = t%16 (float4 lane)
    {
        int ni = t >> 4, i = t & 15;
        const float4* emb4 = (const float4*)emb;
        float4 self4 = __ldg(emb4 + (size_t)s_e[ni] * 16 + i);
        float4 agg = make_float4(0.f, 0.f, 0.f, 0.f);
        #pragma unroll 8
        for (int j = 0; j < SS; j++) {
            float  wj = s_w1[ni][j];
            float4 v  = __ldg(emb4 + (size_t)s_nbr[ni][j] * 16 + i);
            agg.x += wj * v.x; agg.y += wj * v.y; agg.z += wj * v.z; agg.w += wj * v.w;
        }
        buf[ni * 32 + i]      = self4;   // x[k4=0..15] = self
        buf[ni * 32 + 16 + i] = agg;     // x[k4=16..31] = agg
    }
    __syncthreads();

    // Phase 3: MLP. i = t&15 (out quad 4i..4i+3), half = t>>4 (k4 slice of 4)
    int i = t & 15, half = t >> 4;
    float4 acc[8];
    #pragma unroll
    for (int n = 0; n < 8; n++) acc[n] = make_float4(0.f, 0.f, 0.f, 0.f);
    const float4* pw4 = (const float4*)pool_w;
    #pragma unroll
    for (int kk = 0; kk < 4; kk++) {
        int k4 = half * 4 + kk;
        float4 wA = __ldg(pw4 + (size_t)(k4 * 4 + 0) * 16 + i);
        float4 wB = __ldg(pw4 + (size_t)(k4 * 4 + 1) * 16 + i);
        float4 wC = __ldg(pw4 + (size_t)(k4 * 4 + 2) * 16 + i);
        float4 wD = __ldg(pw4 + (size_t)(k4 * 4 + 3) * 16 + i);
        #pragma unroll
        for (int n = 0; n < 8; n++) {
            float4 xv = buf[n * 32 + k4];
            acc[n].x += xv.x * wA.x + xv.y * wB.x + xv.z * wC.x + xv.w * wD.x;
            acc[n].y += xv.x * wA.y + xv.y * wB.y + xv.z * wC.y + xv.w * wD.y;
            acc[n].z += xv.x * wA.z + xv.y * wB.z + xv.z * wC.z + xv.w * wD.z;
            acc[n].w += xv.x * wA.w + xv.y * wB.w + xv.z * wC.w + xv.w * wD.w;
        }
    }
    __syncthreads();                    // all x reads done; reuse buf
    #pragma unroll
    for (int n = 0; n < 8; n++) buf[half * 128 + n * 16 + i] = acc[n];
    __syncthreads();

    // Reduce 8 halves. thread: n = t>>4, i = t&15
    {
        int n = t >> 4;
        float4 r = buf[n * 16 + i];
        #pragma unroll
        for (int h = 1; h < 8; h++) {
            float4 p = buf[h * 128 + n * 16 + i];
            r.x += p.x; r.y += p.y; r.z += p.z; r.w += p.w;
        }
        float4 bias = __ldg(((const float4*)pool_b) + i);
        r.x = fmaxf(r.x + bias.x, 0.f); r.y = fmaxf(r.y + bias.y, 0.f);
        r.z = fmaxf(r.z + bias.z, 0.f); r.w = fmaxf(r.w + bias.w, 0.f);
        ((float4*)g_h1)[(size_t)(node0 + n) * 16 + i] = r;
    }
}

// ---------------------------------------------------------------------------
// K4: 4 items per 256-thread block. grid = 512.
// ---------------------------------------------------------------------------
__global__ void __launch_bounds__(256) k_final(
    const int*   __restrict__ item_inputs,
    const int*   __restrict__ adj_item,
    const float* __restrict__ adj_adam,
    const float* __restrict__ emb,
    const float* __restrict__ pool_w,
    const float* __restrict__ pool_b,
    const float* __restrict__ fc1_w,    // [128][32]
    const float* __restrict__ fc1_b,
    const float* __restrict__ fc2_w,
    const float* __restrict__ fc2_b)
{
    __shared__ float  s_w0[4][SS];
    __shared__ int    s_nbr0[4][SS];
    __shared__ int    s_item[4];
    __shared__ float4 s_x1[4][32];      // pool1 input [self||agg]
    __shared__ float4 s_x2[4][32];      // pool2 input [h0||agg2]
    __shared__ float4 s_fc[4][32];      // fc input [user||item]
    __shared__ float4 s_part[16][4][16];// 16 KB MLP partials (reused by fc)

    int t = threadIdx.x, warp = t >> 5, lane = t & 31;
    int b0 = blockIdx.x * 4;

    // Phase A: level-0 softmaxes (warps 0-3) + user emb load (warps 4-7)
    if (warp < 4) {
        int item = __ldg(item_inputs + b0 + warp);
        if (lane == 0) s_item[warp] = item;
        float a  = __ldg(adj_adam + (size_t)item * SS + lane);
        int  nbr = __ldg(adj_item + (size_t)item * SS + lane);
        float m = a;
        #pragma unroll
        for (int o = 16; o > 0; o >>= 1) m = fmaxf(m, __shfl_xor_sync(0xffffffffu, m, o));
        float ex = expf(a - m);
        float ssum = ex;
        #pragma unroll
        for (int o = 16; o > 0; o >>= 1) ssum += __shfl_xor_sync(0xffffffffu, ssum, o);
        s_w0[warp][lane]   = ex / ssum;
        s_nbr0[warp][lane] = nbr;
    } else {
        int q = warp - 4;
        float* fcx = (float*)s_fc[q];
        fcx[lane]      = g_user[(b0 + q) * DIM + lane];
        fcx[32 + lane] = g_user[(b0 + q) * DIM + 32 + lane];
    }
    __syncthreads();

    // Phase B: pool1 input (self + agg over emb) and pool2 agg over g_h1
    {
        int q = t >> 6, d = t & 63;
        int item = s_item[q];
        float* x1 = (float*)s_x1[q];
        float* x2 = (float*)s_x2[q];
        x1[d] = __ldg(emb + (size_t)item * DIM + d);
        float agg = 0.f, agg2 = 0.f;
        const float* h1b = g_h1 + (size_t)(b0 + q) * SS * DIM;
        #pragma unroll 8
        for (int j = 0; j < SS; j++) {
            float wj = s_w0[q][j];
            agg  += wj * __ldg(emb + (size_t)s_nbr0[q][j] * DIM + d);
            agg2 += wj * h1b[j * DIM + d];
        }
        x1[DIM + d] = agg;
        x2[DIM + d] = agg2;
    }
    __syncthreads();

    // Phase C: pool1 MLP. i = t&15 (out quad), half = t>>4 (k4 slice of 2)
    int i = t & 15, half = t >> 4;
    const float4* pw4 = (const float4*)pool_w;
    {
        float4 acc[4];
        #pragma unroll
        for (int q = 0; q < 4; q++) acc[q] = make_float4(0.f, 0.f, 0.f, 0.f);
        #pragma unroll
        for (int kk = 0; kk < 2; kk++) {
            int k4 = half * 2 + kk;
            float4 wA = __ldg(pw4 + (size_t)(k4 * 4 + 0) * 16 + i);
            float4 wB = __ldg(pw4 + (size_t)(k4 * 4 + 1) * 16 + i);
            float4 wC = __ldg(pw4 + (size_t)(k4 * 4 + 2) * 16 + i);
            float4 wD = __ldg(pw4 + (size_t)(k4 * 4 + 3) * 16 + i);
            #pragma unroll
            for (int q = 0; q < 4; q++) {
                float4 xv = s_x1[q][k4];
                acc[q].x += xv.x * wA.x + xv.y * wB.x + xv.z * wC.x + xv.w * wD.x;
                acc[q].y += xv.x * wA.y + xv.y * wB.y + xv.z * wC.y + xv.w * wD.y;
                acc[q].z += xv.x * wA.z + xv.y * wB.z + xv.z * wC.z + xv.w * wD.z;
                acc[q].w += xv.x * wA.w + xv.y * wB.w + xv.z * wC.w + xv.w * wD.w;
            }
        }
        #pragma unroll
        for (int q = 0; q < 4; q++) s_part[half][q][i] = acc[q];
    }
    __syncthreads();
    if (t < 64) {    // reduce -> h0 (lower half of pool2 input)
        int q = t >> 4, ii = t & 15;
        float4 r = s_part[0][q][ii];
        #pragma unroll
        for (int h = 1; h < 16; h++) {
            float4 p = s_part[h][q][ii];
            r.x += p.x; r.y += p.y; r.z += p.z; r.w += p.w;
        }
        float4 bias = __ldg(((const float4*)pool_b) + ii);
        r.x = fmaxf(r.x + bias.x, 0.f); r.y = fmaxf(r.y + bias.y, 0.f);
        r.z = fmaxf(r.z + bias.z, 0.f); r.w = fmaxf(r.w + bias.w, 0.f);
        s_x2[q][ii] = r;
    }
    __syncthreads();

    // Phase D: pool2 MLP -> item emb (upper half of fc input)
    {
        float4 acc[4];
        #pragma unroll
        for (int q = 0; q < 4; q++) acc[q] = make_float4(0.f, 0.f, 0.f, 0.f);
        #pragma unroll
        for (int kk = 0; kk < 2; kk++) {
            int k4 = half * 2 + kk;
            float4 wA = __ldg(pw4 + (size_t)(k4 * 4 + 0) * 16 + i);
            float4 wB = __ldg(pw4 + (size_t)(k4 * 4 + 1) * 16 + i);
            float4 wC = __ldg(pw4 + (size_t)(k4 * 4 + 2) * 16 + i);
            float4 wD = __ldg(pw4 + (size_t)(k4 * 4 + 3) * 16 + i);
            #pragma unroll
            for (int q = 0; q < 4; q++) {
                float4 xv = s_x2[q][k4];
                acc[q].x += xv.x * wA.x + xv.y * wB.x + xv.z * wC.x + xv.w * wD.x;
                acc[q].y += xv.x * wA.y + xv.y * wB.y + xv.z * wC.y + xv.w * wD.y;
                acc[q].z += xv.x * wA.z + xv.y * wB.z + xv.z * wC.z + xv.w * wD.z;
                acc[q].w += xv.x * wA.w + xv.y * wB.w + xv.z * wC.w + xv.w * wD.w;
            }
        }
        #pragma unroll
        for (int q = 0; q < 4; q++) s_part[half][q][i] = acc[q];
    }
    __syncthreads();
    if (t < 64) {
        int q = t >> 4, ii = t & 15;
        float4 r = s_part[0][q][ii];
        #pragma unroll
        for (int h = 1; h < 16; h++) {
            float4 p = s_part[h][q][ii];
            r.x += p.x; r.y += p.y; r.z += p.z; r.w += p.w;
        }
        float4 bias = __ldg(((const float4*)pool_b) + ii);
        r.x = fmaxf(r.x + bias.x, 0.f); r.y = fmaxf(r.y + bias.y, 0.f);
        r.z = fmaxf(r.z + bias.z, 0.f); r.w = fmaxf(r.w + bias.w, 0.f);
        s_fc[q][16 + ii] = r;
    }
    __syncthreads();

    // Phase E: fc1 (128->32). o = t&31, h8 = t>>5 (k slice of 16), 4 items
    {
        int o = t & 31, h8 = t >> 5;
        float acc[4] = {0.f, 0.f, 0.f, 0.f};
        const float* fcx0 = (const float*)s_fc[0];
        const float* fcx1 = (const float*)s_fc[1];
        const float* fcx2 = (const float*)s_fc[2];
        const float* fcx3 = (const float*)s_fc[3];
        #pragma unroll
        for (int kk = 0; kk < 16; kk++) {
            int k = h8 * 16 + kk;
            float w = __ldg(fc1_w + k * 32 + o);
            acc[0] += fcx0[k] * w;
            acc[1] += fcx1[k] * w;
            acc[2] += fcx2[k] * w;
            acc[3] += fcx3[k] * w;
        }
        float* pf = (float*)s_part;     // [8][4][32]
        #pragma unroll
        for (int q = 0; q < 4; q++) pf[h8 * 128 + q * 32 + o] = acc[q];
    }
    __syncthreads();
    if (t < 128) {                      // warp = item
        int q = t >> 5, o = lane;
        const float* pf = (const float*)s_part;
        float y = __ldg(fc1_b + o);
        #pragma unroll
        for (int h = 0; h < 8; h++) y += pf[h * 128 + q * 32 + o];
        y = fmaxf(y, 0.f);
        float p = y * __ldg(fc2_w + o);
        #pragma unroll
        for (int o2 = 16; o2 > 0; o2 >>= 1) p += __shfl_xor_sync(0xffffffffu, p, o2);
        if (o == 0) g_scores[b0 + q] = p + __ldg(fc2_b);
    }
}

// ---------------------------------------------------------------------------
// K5: batch softmax, shuffle-based
// ---------------------------------------------------------------------------
__global__ void k_softmax(float* __restrict__ out) {
    __shared__ float rmax[32], rsum[32];
    int t = threadIdx.x, lane = t & 31, w = t >> 5;
    float a0 = g_scores[t], a1 = g_scores[t + 1024];
    float m = fmaxf(a0, a1);
    #pragma unroll
    for (int o = 16; o > 0; o >>= 1) m = fmaxf(m, __shfl_xor_sync(0xffffffffu, m, o));
    if (lane == 0) rmax[w] = m;
    __syncthreads();
    if (t < 32) {
        float mm = rmax[t];
        #pragma unroll
        for (int o = 16; o > 0; o >>= 1) mm = fmaxf(mm, __shfl_xor_sync(0xffffffffu, mm, o));
        rmax[t] = mm;
    }
    __syncthreads();
    float gm = rmax[0];
    float e0 = expf(a0 - gm), e1 = expf(a1 - gm);
    float s = e0 + e1;
    #pragma unroll
    for (int o = 16; o > 0; o >>= 1) s += __shfl_xor_sync(0xffffffffu, s, o);
    if (lane == 0) rsum[w] = s;
    __syncthreads();
    if (t < 32) {
        float ss = rsum[t];
        #pragma unroll
        for (int o = 16; o > 0; o >>= 1) ss += __shfl_xor_sync(0xffffffffu, ss, o);
        rsum[t] = ss;
    }
    __syncthreads();
    float inv = 1.f / rsum[0];
    out[t]        = e0 * inv;
    out[t + 1024] = e1 * inv;
}

// ---------------------------------------------------------------------------
extern "C" void kernel_launch(void* const* d_in, const int* in_sizes, int n_in,
                              void* d_out, int out_size) {
    const int*   user_inputs = (const int*)  d_in[0];
    const int*   item_inputs = (const int*)  d_in[1];
    const int*   n_idxs      = (const int*)  d_in[2];
    const float* emb         = (const float*)d_in[3];
    const int*   adj_item    = (const int*)  d_in[4];
    const float* adj_adam    = (const float*)d_in[5];
    const float* pool_w      = (const float*)d_in[6];
    const float* pool_b      = (const float*)d_in[7];
    const float* fc1_w       = (const float*)d_in[8];
    const float* fc1_b       = (const float*)d_in[9];
    const float* fc2_w       = (const float*)d_in[10];
    const float* fc2_b       = (const float*)d_in[11];
    float* out = (float*)d_out;

    k_maxn<<<1, 256>>>(n_idxs);
    k_user<<<BB, 128>>>(user_inputs, n_idxs, emb);
    k_h1<<<BB * SS / 8, 128>>>(item_inputs, adj_item, adj_adam, emb, pool_w, pool_b);
    k_final<<<BB / 4, 256>>>(item_inputs, adj_item, adj_adam, emb,
                             pool_w, pool_b, fc1_w, fc1_b, fc2_w, fc2_b);
    k_softmax<<<1, 1024>>>(out);
}

// round 5
// speedup vs baseline: 1.6660x; 1.2231x over previous
#include <cuda_runtime.h>

#define BB   2048
#define HIST 50
#define DIM  64
#define SS   32

__device__ float g_user[BB*DIM];            // RAW sums (unscaled)
__device__ float g_h1[(size_t)BB*SS*DIM];   // 16 MB level-1 pooled vectors
__device__ float g_scores[BB];
__device__ float g_maxn;

// ---------------------------------------------------------------------------
// K1: max(n_idxs)
// ---------------------------------------------------------------------------
__global__ void k_maxn(const int* __restrict__ n_idxs) {
    __shared__ int sm[256];
    int m = 0;
    for (int i = threadIdx.x; i < BB; i += 256) m = max(m, __ldg(n_idxs + i));
    sm[threadIdx.x] = m;
    __syncthreads();
    for (int s = 128; s > 0; s >>= 1) {
        if (threadIdx.x < s) sm[threadIdx.x] = max(sm[threadIdx.x], sm[threadIdx.x + s]);
        __syncthreads();
    }
    if (threadIdx.x == 0) g_maxn = (float)sm[0];
}

// ---------------------------------------------------------------------------
// K2: user embedding RAW sum. grid=B, block=128. (scale by 1/maxn in k_final)
// ---------------------------------------------------------------------------
__global__ void __launch_bounds__(128) k_user(const int* __restrict__ user_inputs,
                                              const int* __restrict__ n_idxs,
                                              const float* __restrict__ emb) {
    __shared__ float4 red[8][16];
    int b = blockIdx.x, t = threadIdx.x;
    int i = t & 15, h = t >> 4;
    int n = __ldg(n_idxs + b);
    const float4* emb4 = (const float4*)emb;
    const int* row = user_inputs + b * HIST;
    float4 acc = make_float4(0.f, 0.f, 0.f, 0.f);
    for (int p = h; p < n; p += 8) {
        int idx = __ldg(row + p);
        float4 v = __ldg(emb4 + (size_t)idx * 16 + i);
        acc.x += v.x; acc.y += v.y; acc.z += v.z; acc.w += v.w;
    }
    red[h][i] = acc;
    __syncthreads();
    if (h == 0) {
        float4 s = red[0][i];
        #pragma unroll
        for (int q = 1; q < 8; q++) {
            float4 v = red[q][i];
            s.x += v.x; s.y += v.y; s.z += v.z; s.w += v.w;
        }
        ((float4*)g_user)[(size_t)b * 16 + i] = s;
    }
}

// ---------------------------------------------------------------------------
// K3: level-1 pooling, 8 nodes per 128-thread block. grid = 8192.
// launch_bounds(128,8): cap at 64 regs -> 8 blocks/SM (50% occ) for gathers.
// ---------------------------------------------------------------------------
__global__ void __launch_bounds__(128, 8) k_h1(
    const int*   __restrict__ item_inputs,
    const int*   __restrict__ adj_item,
    const float* __restrict__ adj_adam,
    const float* __restrict__ emb,
    const float* __restrict__ pool_w,   // [128][64]
    const float* __restrict__ pool_b)   // [64]
{
    __shared__ float  s_w1[8][SS];
    __shared__ int    s_nbr[8][SS];
    __shared__ int    s_e[8];
    __shared__ float4 buf[1024];        // 16 KB: x-tiles then MLP partials

    int t = threadIdx.x, warp = t >> 5, lane = t & 31;
    int node0 = blockIdx.x * 8;
    int b = node0 >> 5;
    int nn0 = node0 & 31;
    int item = __ldg(item_inputs + b);

    // Phase 1: 8 level-1 softmaxes (2 per warp)
    #pragma unroll
    for (int q = 0; q < 2; q++) {
        int ni = warp * 2 + q;
        int e  = __ldg(adj_item + (size_t)item * SS + nn0 + ni);
        float a  = __ldg(adj_adam + (size_t)e * SS + lane);
        int  nbr = __ldg(adj_item + (size_t)e * SS + lane);
        float m = a;
        #pragma unroll
        for (int o = 16; o > 0; o >>= 1) m = fmaxf(m, __shfl_xor_sync(0xffffffffu, m, o));
        float ex = expf(a - m);
        float ssum = ex;
        #pragma unroll
        for (int o = 16; o > 0; o >>= 1) ssum += __shfl_xor_sync(0xffffffffu, ssum, o);
        s_w1[ni][lane]  = ex / ssum;
        s_nbr[ni][lane] = nbr;
        if (lane == 0) s_e[ni] = e;
    }
    __syncthreads();

    // Phase 2: gathers. ni = t/16 (node), i = t%16 (float4 lane)
    {
        int ni = t >> 4, i = t & 15;
        const float4* emb4 = (const float4*)emb;
        float4 self4 = __ldg(emb4 + (size_t)s_e[ni] * 16 + i);
        float4 agg = make_float4(0.f, 0.f, 0.f, 0.f);
        #pragma unroll 8
        for (int j = 0; j < SS; j++) {
            float  wj = s_w1[ni][j];
            float4 v  = __ldg(emb4 + (size_t)s_nbr[ni][j] * 16 + i);
            agg.x += wj * v.x; agg.y += wj * v.y; agg.z += wj * v.z; agg.w += wj * v.w;
        }
        buf[ni * 32 + i]      = self4;
        buf[ni * 32 + 16 + i] = agg;
    }
    __syncthreads();

    // Phase 3: MLP. i = t&15 (out quad), half = t>>4 (k4-slice of 4)
    int i = t & 15, half = t >> 4;
    float4 acc[8];
    #pragma unroll
    for (int n = 0; n < 8; n++) acc[n] = make_float4(0.f, 0.f, 0.f, 0.f);
    const float4* pw4 = (const float4*)pool_w;
    #pragma unroll
    for (int kk = 0; kk < 4; kk++) {
        int k4 = half * 4 + kk;
        float4 wA = __ldg(pw4 + (size_t)(k4 * 4 + 0) * 16 + i);
        float4 wB = __ldg(pw4 + (size_t)(k4 * 4 + 1) * 16 + i);
        float4 wC = __ldg(pw4 + (size_t)(k4 * 4 + 2) * 16 + i);
        float4 wD = __ldg(pw4 + (size_t)(k4 * 4 + 3) * 16 + i);
        #pragma unroll
        for (int n = 0; n < 8; n++) {
            float4 xv = buf[n * 32 + k4];
            acc[n].x += xv.x * wA.x + xv.y * wB.x + xv.z * wC.x + xv.w * wD.x;
            acc[n].y += xv.x * wA.y + xv.y * wB.y + xv.z * wC.y + xv.w * wD.y;
            acc[n].z += xv.x * wA.z + xv.y * wB.z + xv.z * wC.z + xv.w * wD.z;
            acc[n].w += xv.x * wA.w + xv.y * wB.w + xv.z * wC.w + xv.w * wD.w;
        }
    }
    __syncthreads();
    #pragma unroll
    for (int n = 0; n < 8; n++) buf[half * 128 + n * 16 + i] = acc[n];
    __syncthreads();

    // Reduce 8 halves. n = t>>4, i = t&15
    {
        int n = t >> 4;
        float4 r = buf[n * 16 + i];
        #pragma unroll
        for (int h = 1; h < 8; h++) {
            float4 p = buf[h * 128 + n * 16 + i];
            r.x += p.x; r.y += p.y; r.z += p.z; r.w += p.w;
        }
        float4 bias = __ldg(((const float4*)pool_b) + i);
        r.x = fmaxf(r.x + bias.x, 0.f); r.y = fmaxf(r.y + bias.y, 0.f);
        r.z = fmaxf(r.z + bias.z, 0.f); r.w = fmaxf(r.w + bias.w, 0.f);
        ((float4*)g_h1)[(size_t)(node0 + n) * 16 + i] = r;
    }
}

// ---------------------------------------------------------------------------
// K4: 2 items per 128-thread block. grid = 1024. Low regs -> high occupancy.
// ---------------------------------------------------------------------------
__global__ void __launch_bounds__(128, 8) k_final(
    const int*   __restrict__ item_inputs,
    const int*   __restrict__ adj_item,
    const float* __restrict__ adj_adam,
    const float* __restrict__ emb,
    const float* __restrict__ pool_w,
    const float* __restrict__ pool_b,
    const float* __restrict__ fc1_w,    // [128][32]
    const float* __restrict__ fc1_b,
    const float* __restrict__ fc2_w,
    const float* __restrict__ fc2_b)
{
    __shared__ float  s_w0[2][SS];
    __shared__ int    s_nbr0[2][SS];
    __shared__ int    s_item[2];
    __shared__ float4 s_x1[2][32];       // pool1 input [self||agg]
    __shared__ float4 s_x2[2][32];       // pool2 input [h0||agg2]
    __shared__ float4 s_fc[2][32];       // fc input [user||item]
    __shared__ float4 s_part[8][2][16];  // 4 KB MLP partials

    int t = threadIdx.x, warp = t >> 5, lane = t & 31;
    int b0 = blockIdx.x * 2;

    // Phase A: warps 0-1 softmaxes; warps 2-3 load user emb (scaled)
    if (warp < 2) {
        int item = __ldg(item_inputs + b0 + warp);
        if (lane == 0) s_item[warp] = item;
        float a  = __ldg(adj_adam + (size_t)item * SS + lane);
        int  nbr = __ldg(adj_item + (size_t)item * SS + lane);
        float m = a;
        #pragma unroll
        for (int o = 16; o > 0; o >>= 1) m = fmaxf(m, __shfl_xor_sync(0xffffffffu, m, o));
        float ex = expf(a - m);
        float ssum = ex;
        #pragma unroll
        for (int o = 16; o > 0; o >>= 1) ssum += __shfl_xor_sync(0xffffffffu, ssum, o);
        s_w0[warp][lane]   = ex / ssum;
        s_nbr0[warp][lane] = nbr;
    } else {
        int q = warp - 2;
        float inv = 1.f / g_maxn;
        float* fcx = (float*)s_fc[q];
        fcx[lane]      = g_user[(b0 + q) * DIM + lane] * inv;
        fcx[32 + lane] = g_user[(b0 + q) * DIM + 32 + lane] * inv;
    }
    __syncthreads();

    // Phase B: q = t>>6 (item), d = t&63. agg over emb + agg2 over g_h1
    {
        int q = t >> 6, d = t & 63;
        int item = s_item[q];
        float* x1 = (float*)s_x1[q];
        float* x2 = (float*)s_x2[q];
        x1[d] = __ldg(emb + (size_t)item * DIM + d);
        float agg = 0.f, agg2 = 0.f;
        const float* h1b = g_h1 + (size_t)(b0 + q) * SS * DIM;
        #pragma unroll 8
        for (int j = 0; j < SS; j++) {
            float wj = s_w0[q][j];
            agg  += wj * __ldg(emb + (size_t)s_nbr0[q][j] * DIM + d);
            agg2 += wj * h1b[j * DIM + d];
        }
        x1[DIM + d] = agg;
        x2[DIM + d] = agg2;
    }
    __syncthreads();

    // Phase C: pool1 MLP. i = t&15, half = t>>4 (k4-slice of 4)
    int i = t & 15, half = t >> 4;
    const float4* pw4 = (const float4*)pool_w;
    {
        float4 a0 = make_float4(0.f,0.f,0.f,0.f), a1 = make_float4(0.f,0.f,0.f,0.f);
        #pragma unroll
        for (int kk = 0; kk < 4; kk++) {
            int k4 = half * 4 + kk;
            float4 wA = __ldg(pw4 + (size_t)(k4 * 4 + 0) * 16 + i);
            float4 wB = __ldg(pw4 + (size_t)(k4 * 4 + 1) * 16 + i);
            float4 wC = __ldg(pw4 + (size_t)(k4 * 4 + 2) * 16 + i);
            float4 wD = __ldg(pw4 + (size_t)(k4 * 4 + 3) * 16 + i);
            float4 x0 = s_x1[0][k4];
            a0.x += x0.x*wA.x + x0.y*wB.x + x0.z*wC.x + x0.w*wD.x;
            a0.y += x0.x*wA.y + x0.y*wB.y + x0.z*wC.y + x0.w*wD.y;
            a0.z += x0.x*wA.z + x0.y*wB.z + x0.z*wC.z + x0.w*wD.z;
            a0.w += x0.x*wA.w + x0.y*wB.w + x0.z*wC.w + x0.w*wD.w;
            float4 x1v = s_x1[1][k4];
            a1.x += x1v.x*wA.x + x1v.y*wB.x + x1v.z*wC.x + x1v.w*wD.x;
            a1.y += x1v.x*wA.y + x1v.y*wB.y + x1v.z*wC.y + x1v.w*wD.y;
            a1.z += x1v.x*wA.z + x1v.y*wB.z + x1v.z*wC.z + x1v.w*wD.z;
            a1.w += x1v.x*wA.w + x1v.y*wB.w + x1v.z*wC.w + x1v.w*wD.w;
        }
        s_part[half][0][i] = a0;
        s_part[half][1][i] = a1;
    }
    __syncthreads();
    if (t < 32) {       // reduce -> h0 (lower half of pool2 input)
        int q = t >> 4, ii = t & 15;
        float4 r = s_part[0][q][ii];
        #pragma unroll
        for (int h = 1; h < 8; h++) {
            float4 p = s_part[h][q][ii];
            r.x += p.x; r.y += p.y; r.z += p.z; r.w += p.w;
        }
        float4 bias = __ldg(((const float4*)pool_b) + ii);
        r.x = fmaxf(r.x + bias.x, 0.f); r.y = fmaxf(r.y + bias.y, 0.f);
        r.z = fmaxf(r.z + bias.z, 0.f); r.w = fmaxf(r.w + bias.w, 0.f);
        s_x2[q][ii] = r;
    }
    __syncthreads();

    // Phase D: pool2 MLP -> item emb (upper half of fc input)
    {
        float4 a0 = make_float4(0.f,0.f,0.f,0.f), a1 = make_float4(0.f,0.f,0.f,0.f);
        #pragma unroll
        for (int kk = 0; kk < 4; kk++) {
            int k4 = half * 4 + kk;
            float4 wA = __ldg(pw4 + (size_t)(k4 * 4 + 0) * 16 + i);
            float4 wB = __ldg(pw4 + (size_t)(k4 * 4 + 1) * 16 + i);
            float4 wC = __ldg(pw4 + (size_t)(k4 * 4 + 2) * 16 + i);
            float4 wD = __ldg(pw4 + (size_t)(k4 * 4 + 3) * 16 + i);
            float4 x0 = s_x2[0][k4];
            a0.x += x0.x*wA.x + x0.y*wB.x + x0.z*wC.x + x0.w*wD.x;
            a0.y += x0.x*wA.y + x0.y*wB.y + x0.z*wC.y + x0.w*wD.y;
            a0.z += x0.x*wA.z + x0.y*wB.z + x0.z*wC.z + x0.w*wD.z;
            a0.w += x0.x*wA.w + x0.y*wB.w + x0.z*wC.w + x0.w*wD.w;
            float4 x1v = s_x2[1][k4];
            a1.x += x1v.x*wA.x + x1v.y*wB.x + x1v.z*wC.x + x1v.w*wD.x;
            a1.y += x1v.x*wA.y + x1v.y*wB.y + x1v.z*wC.y + x1v.w*wD.y;
            a1.z += x1v.x*wA.z + x1v.y*wB.z + x1v.z*wC.z + x1v.w*wD.z;
            a1.w += x1v.x*wA.w + x1v.y*wB.w + x1v.z*wC.w + x1v.w*wD.w;
        }
        s_part[half][0][i] = a0;
        s_part[half][1][i] = a1;
    }
    __syncthreads();
    if (t < 32) {
        int q = t >> 4, ii = t & 15;
        float4 r = s_part[0][q][ii];
        #pragma unroll
        for (int h = 1; h < 8; h++) {
            float4 p = s_part[h][q][ii];
            r.x += p.x; r.y += p.y; r.z += p.z; r.w += p.w;
        }
        float4 bias = __ldg(((const float4*)pool_b) + ii);
        r.x = fmaxf(r.x + bias.x, 0.f); r.y = fmaxf(r.y + bias.y, 0.f);
        r.z = fmaxf(r.z + bias.z, 0.f); r.w = fmaxf(r.w + bias.w, 0.f);
        s_fc[q][16 + ii] = r;
    }
    __syncthreads();

    // Phase E: fc1 (128->32). o = t&31, h4 = t>>5 (k-slice of 32)
    {
        int o = t & 31, h4 = t >> 5;
        float a0 = 0.f, a1 = 0.f;
        const float* fcx0 = (const float*)s_fc[0];
        const float* fcx1 = (const float*)s_fc[1];
        #pragma unroll 8
        for (int kk = 0; kk < 32; kk++) {
            int k = h4 * 32 + kk;
            float w = __ldg(fc1_w + k * 32 + o);
            a0 += fcx0[k] * w;
            a1 += fcx1[k] * w;
        }
        float* pf = (float*)s_part;     // [4][2][32]
        pf[h4 * 64 + o]      = a0;
        pf[h4 * 64 + 32 + o] = a1;
    }
    __syncthreads();
    if (t < 64) {                       // warp q = item
        int q = t >> 5, o = lane;
        const float* pf = (const float*)s_part;
        float y = __ldg(fc1_b + o);
        #pragma unroll
        for (int h = 0; h < 4; h++) y += pf[h * 64 + q * 32 + o];
        y = fmaxf(y, 0.f);
        float p = y * __ldg(fc2_w + o);
        #pragma unroll
        for (int o2 = 16; o2 > 0; o2 >>= 1) p += __shfl_xor_sync(0xffffffffu, p, o2);
        if (o == 0) g_scores[b0 + q] = p + __ldg(fc2_b);
    }
}

// ---------------------------------------------------------------------------
// K5: batch softmax, shuffle-based
// ---------------------------------------------------------------------------
__global__ void k_softmax(float* __restrict__ out) {
    __shared__ float rmax[32], rsum[32];
    int t = threadIdx.x, lane = t & 31, w = t >> 5;
    float a0 = g_scores[t], a1 = g_scores[t + 1024];
    float m = fmaxf(a0, a1);
    #pragma unroll
    for (int o = 16; o > 0; o >>= 1) m = fmaxf(m, __shfl_xor_sync(0xffffffffu, m, o));
    if (lane == 0) rmax[w] = m;
    __syncthreads();
    if (t < 32) {
        float mm = rmax[t];
        #pragma unroll
        for (int o = 16; o > 0; o >>= 1) mm = fmaxf(mm, __shfl_xor_sync(0xffffffffu, mm, o));
        rmax[t] = mm;
    }
    __syncthreads();
    float gm = rmax[0];
    float e0 = expf(a0 - gm), e1 = expf(a1 - gm);
    float s = e0 + e1;
    #pragma unroll
    for (int o = 16; o > 0; o >>= 1) s += __shfl_xor_sync(0xffffffffu, s, o);
    if (lane == 0) rsum[w] = s;
    __syncthreads();
    if (t < 32) {
        float ss = rsum[t];
        #pragma unroll
        for (int o = 16; o > 0; o >>= 1) ss += __shfl_xor_sync(0xffffffffu, ss, o);
        rsum[t] = ss;
    }
    __syncthreads();
    float inv = 1.f / rsum[0];
    out[t]        = e0 * inv;
    out[t + 1024] = e1 * inv;
}

// ---------------------------------------------------------------------------
// Launch: fork k_maxn+k_user onto a side stream, overlapped with k_h1.
// Stream/events created on the FIRST call (the correctness run precedes
// graph capture, so creation never happens during capture).
// ---------------------------------------------------------------------------
extern "C" void kernel_launch(void* const* d_in, const int* in_sizes, int n_in,
                              void* d_out, int out_size) {
    static cudaStream_t s2 = nullptr;
    static cudaEvent_t  ev_fork = nullptr, ev_join = nullptr;
    if (s2 == nullptr) {
        cudaStreamCreateWithFlags(&s2, cudaStreamNonBlocking);
        cudaEventCreateWithFlags(&ev_fork, cudaEventDisableTiming);
        cudaEventCreateWithFlags(&ev_join, cudaEventDisableTiming);
    }

    const int*   user_inputs = (const int*)  d_in[0];
    const int*   item_inputs = (const int*)  d_in[1];
    const int*   n_idxs      = (const int*)  d_in[2];
    const float* emb         = (const float*)d_in[3];
    const int*   adj_item    = (const int*)  d_in[4];
    const float* adj_adam    = (const float*)d_in[5];
    const float* pool_w      = (const float*)d_in[6];
    const float* pool_b      = (const float*)d_in[7];
    const float* fc1_w       = (const float*)d_in[8];
    const float* fc1_b       = (const float*)d_in[9];
    const float* fc2_w       = (const float*)d_in[10];
    const float* fc2_b       = (const float*)d_in[11];
    float* out = (float*)d_out;

    // fork
    cudaEventRecord(ev_fork, 0);
    cudaStreamWaitEvent(s2, ev_fork, 0);

    // side stream: maxn + user (independent of h1)
    k_maxn<<<1, 256, 0, s2>>>(n_idxs);
    k_user<<<BB, 128, 0, s2>>>(user_inputs, n_idxs, emb);
    cudaEventRecord(ev_join, s2);

    // main stream: the big gather/MLP kernel
    k_h1<<<BB * SS / 8, 128>>>(item_inputs, adj_item, adj_adam, emb, pool_w, pool_b);

    // join, then finalize
    cudaStreamWaitEvent(0, ev_join, 0);
    k_final<<<BB / 2, 128>>>(item_inputs, adj_item, adj_adam, emb,
                             pool_w, pool_b, fc1_w, fc1_b, fc2_w, fc2_b);
    k_softmax<<<1, 1024>>>(out);
}